// round 2
// baseline (speedup 1.0000x reference)
#include <cuda_runtime.h>
#include <cuda_bf16.h>

// out[b, 1+d, p] = x[b, c, hx(p)*16+pi, hy(p)*16+pj] + pos[1+d, p]
//   where d = c*256 + pi*16 + pj, (hx,hy) = hilbert_d2xy(32, p)
// out[b, 0, e]   = cls[e] + pos[0, e]   (fused into ptile==0,dtile==0 CTA)
//
// Tiled transpose: CTA = 32 patches (p) x 128 d. Swizzled smem, conflict-free
// both phases, coalesced gmem on both sides. Streaming hints keep pos in L2.

#define PT 32
#define DT 128

__global__ __launch_bounds__(256) void hilbert_main_kernel(
    const float* __restrict__ x,
    const float* __restrict__ cls,
    const float* __restrict__ pos,
    float* __restrict__ out)
{
    __shared__ float sm[DT * PT];      // addr = d*32 + (pl ^ (d>>2) ^ (d&3))
    __shared__ int pbase[PT];

    const int ptile = blockIdx.x;      // 0..31
    const int dtile = blockIdx.y;      // 0..7
    const int b     = blockIdx.z;      // 0..63
    const int tid   = threadIdx.x;

    const int c   = dtile >> 1;        // channel (d-tile of 128 = half a channel)
    const int pi0 = (dtile & 1) * 8;   // starting patch row within channel
    const int p0  = ptile * PT;
    const int d0  = dtile * DT;
    const long out_b = (long)b * (1025L * 1024L);

    // Hilbert d2xy for this tile's 32 patches (N=32, 5 iterations)
    if (tid < PT) {
        int t = p0 + tid;
        int hx = 0, hy = 0;
        #pragma unroll
        for (int s = 1; s < 32; s <<= 1) {
            int rx = 1 & (t >> 1);
            int ry = 1 & (t ^ rx);
            if (ry == 0) {
                if (rx == 1) { hx = s - 1 - hx; hy = s - 1 - hy; }
                int tmp = hx; hx = hy; hy = tmp;
            }
            hx += s * rx;
            hy += s * ry;
            t >>= 2;
        }
        // x offset of (b, c, hx*16 + pi0, hy*16)
        pbase[tid] = ((b * 4 + c) * 512 + hx * 16 + pi0) * 512 + hy * 16;
    }

    // Fused row0: out[b, 0, :] = cls + pos[0, :]  (one CTA per batch)
    if (ptile == 0 && dtile == 0) {
        float4 cv = *reinterpret_cast<const float4*>(cls + tid * 4);
        float4 pv = *reinterpret_cast<const float4*>(pos + tid * 4);
        cv.x += pv.x; cv.y += pv.y; cv.z += pv.z; cv.w += pv.w;
        *reinterpret_cast<float4*>(out + out_b + tid * 4) = cv;
    }
    __syncthreads();

    // ---- Load phase: 32 patches x 128 floats = 1024 float4 loads ----
    // warp covers one patch slab: 8 rows x 64B contiguous -> full sectors
    #pragma unroll
    for (int i = 0; i < 4; i++) {
        int idx = i * 256 + tid;
        int pl  = idx >> 5;            // patch-local 0..31 (const per warp)
        int f   = idx & 31;            // float4 slot 0..31 within patch slab
        const float4 v = __ldcs(reinterpret_cast<const float4*>(
            x + pbase[pl] + (f >> 2) * 512 + (f & 3) * 4));
        int dl = f * 4;                // local d of v.x
        // col = pl ^ (d>>2) ^ (d&3) = pl ^ f ^ j  -> banks vary with f: CF
        sm[(dl + 0) * 32 + (pl ^ f ^ 0)] = v.x;
        sm[(dl + 1) * 32 + (pl ^ f ^ 1)] = v.y;
        sm[(dl + 2) * 32 + (pl ^ f ^ 2)] = v.z;
        sm[(dl + 3) * 32 + (pl ^ f ^ 3)] = v.w;
    }
    __syncthreads();

    // ---- Store phase: transpose out, float4 over p ----
    #pragma unroll
    for (int i = 0; i < 4; i++) {
        int idx = i * 256 + tid;
        int d   = idx >> 3;            // 0..127  (d>>2 const per warp)
        int p4  = idx & 7;             // 0..7
        int sw  = (d >> 2) ^ (d & 3);
        float4 r;
        r.x = sm[d * 32 + ((4 * p4 + 0) ^ sw)];
        r.y = sm[d * 32 + ((4 * p4 + 1) ^ sw)];
        r.z = sm[d * 32 + ((4 * p4 + 2) ^ sw)];
        r.w = sm[d * 32 + ((4 * p4 + 3) ^ sw)];
        long row = (long)(1 + d0 + d);
        long col = (long)(p0 + p4 * 4);
        const float4 pe = *reinterpret_cast<const float4*>(pos + row * 1024 + col);
        r.x += pe.x; r.y += pe.y; r.z += pe.z; r.w += pe.w;
        __stcs(reinterpret_cast<float4*>(out + out_b + row * 1024 + col), r);
    }
}

extern "C" void kernel_launch(void* const* d_in, const int* in_sizes, int n_in,
                              void* d_out, int out_size)
{
    // Identify inputs by size (defensive against ordering):
    //   x: 64*4*512*512 = 67108864, cls: 1024, pos: 1025*1024 = 1049600
    const float* x   = nullptr;
    const float* cls = nullptr;
    const float* pos = nullptr;
    for (int i = 0; i < n_in; i++) {
        if (in_sizes[i] == 67108864)     x   = (const float*)d_in[i];
        else if (in_sizes[i] == 1024)    cls = (const float*)d_in[i];
        else if (in_sizes[i] == 1049600) pos = (const float*)d_in[i];
    }
    float* out = (float*)d_out;

    dim3 grid(32, 8, 64);   // p-tiles, d-tiles, batch
    hilbert_main_kernel<<<grid, 256>>>(x, cls, pos, out);
}

// round 3
// speedup vs baseline: 1.2423x; 1.2423x over previous
#include <cuda_runtime.h>
#include <cuda_bf16.h>

// out[b, 1+d, p] = x[b, c, hx(p)*16+pi, hy(p)*16+pj] + pos[1+d, p]
//   where d = c*256 + pi*16 + pj, (hx,hy) = hilbert_d2xy(32, p)
// out[b, 0, e]   = cls[e] + pos[0, e]   (fused into ptile==0,dtile==0 CTA)
//
// Fully vectorized tiled transpose: CTA = 32 p x 128 d. Each thread does a
// 4x4 register micro-transpose; all smem traffic is 128-bit and conflict-free
// (xor swizzle sm4[d*8 + (q ^ ((d>>2)&7))], verified per 8-lane phase).

__global__ __launch_bounds__(256) void hilbert_main_kernel(
    const float* __restrict__ x,
    const float* __restrict__ cls,
    const float* __restrict__ pos,
    float* __restrict__ out)
{
    __shared__ float4 sm4[128 * 8];    // [d][q], q xor-swizzled
    __shared__ int pbase[32];

    const int ptile = blockIdx.x;      // 0..31
    const int dtile = blockIdx.y;      // 0..7
    const int b     = blockIdx.z;      // 0..63
    const int tid   = threadIdx.x;

    const int c   = dtile >> 1;        // channel (d-tile of 128 = half a channel)
    const int pi0 = (dtile & 1) * 8;   // starting patch row within channel
    const int p0  = ptile * 32;
    const int d0  = dtile * 128;
    const long out_b = (long)b * (1025L * 1024L);

    // Hilbert d2xy for this tile's 32 patches (N=32, 5 iterations)
    if (tid < 32) {
        int t = p0 + tid;
        int hx = 0, hy = 0;
        #pragma unroll
        for (int s = 1; s < 32; s <<= 1) {
            int rx = 1 & (t >> 1);
            int ry = 1 & (t ^ rx);
            if (ry == 0) {
                if (rx == 1) { hx = s - 1 - hx; hy = s - 1 - hy; }
                int tmp = hx; hx = hy; hy = tmp;
            }
            hx += s * rx;
            hy += s * ry;
            t >>= 2;
        }
        pbase[tid] = ((b * 4 + c) * 512 + hx * 16 + pi0) * 512 + hy * 16;
    }

    // Fused row0: out[b, 0, :] = cls + pos[0, :]  (one CTA per batch)
    if (ptile == 0 && dtile == 0) {
        float4 cv = *reinterpret_cast<const float4*>(cls + tid * 4);
        float4 pv = *reinterpret_cast<const float4*>(pos + tid * 4);
        cv.x += pv.x; cv.y += pv.y; cv.z += pv.z; cv.w += pv.w;
        *reinterpret_cast<float4*>(out + out_b + tid * 4) = cv;
    }
    __syncthreads();

    // ---- Load phase: thread (q = warp, f = lane) loads float4 (4 d's at
    // offset f) from 4 patches 4q..4q+3, transposes 4x4 in registers, stores
    // four p-major float4s with STS.128.
    {
        const int f = tid & 31;        // float4 slot within patch slab (d = 4f..4f+3)
        const int q = tid >> 5;        // p-quad 0..7
        const float* src = x + (f >> 2) * 512 + (f & 3) * 4;
        const float4 v0 = *reinterpret_cast<const float4*>(src + pbase[4 * q + 0]);
        const float4 v1 = *reinterpret_cast<const float4*>(src + pbase[4 * q + 1]);
        const float4 v2 = *reinterpret_cast<const float4*>(src + pbase[4 * q + 2]);
        const float4 v3 = *reinterpret_cast<const float4*>(src + pbase[4 * q + 3]);
        const int base = 32 * f + (q ^ (f & 7));   // d=4f+j at base + 8j
        sm4[base     ] = make_float4(v0.x, v1.x, v2.x, v3.x);
        sm4[base +  8] = make_float4(v0.y, v1.y, v2.y, v3.y);
        sm4[base + 16] = make_float4(v0.z, v1.z, v2.z, v3.z);
        sm4[base + 24] = make_float4(v0.w, v1.w, v2.w, v3.w);
    }
    __syncthreads();

    // ---- Store phase: one LDS.128 (4 consecutive p at fixed d) + pos add +
    // STG.128 per quad. 4 quads per thread.
    #pragma unroll
    for (int k = 0; k < 4; k++) {
        const int idx = k * 256 + tid;
        const int d   = idx >> 3;      // 0..127 (d>>2 const per warp)
        const int q   = idx & 7;       // p-quad
        float4 r = sm4[d * 8 + (q ^ ((d >> 2) & 7))];
        const long row = (long)(1 + d0 + d);
        const long col = (long)(p0 + q * 4);
        const float4 pe = *reinterpret_cast<const float4*>(pos + row * 1024 + col);
        r.x += pe.x; r.y += pe.y; r.z += pe.z; r.w += pe.w;
        __stcs(reinterpret_cast<float4*>(out + out_b + row * 1024 + col), r);
    }
}

extern "C" void kernel_launch(void* const* d_in, const int* in_sizes, int n_in,
                              void* d_out, int out_size)
{
    // Identify inputs by size (defensive against ordering):
    //   x: 64*4*512*512 = 67108864, cls: 1024, pos: 1025*1024 = 1049600
    const float* x   = nullptr;
    const float* cls = nullptr;
    const float* pos = nullptr;
    for (int i = 0; i < n_in; i++) {
        if (in_sizes[i] == 67108864)     x   = (const float*)d_in[i];
        else if (in_sizes[i] == 1024)    cls = (const float*)d_in[i];
        else if (in_sizes[i] == 1049600) pos = (const float*)d_in[i];
    }
    float* out = (float*)d_out;

    dim3 grid(32, 8, 64);   // p-tiles, d-tiles, batch
    hilbert_main_kernel<<<grid, 256>>>(x, cls, pos, out);
}